// round 1
// baseline (speedup 1.0000x reference)
#include <cuda_runtime.h>

// out[b,i,h,w] = sum_j x[b,j,h,w] - x[b,i,h,w]
// x: fp32 [16, 256, 128, 128]
//
// Strategy: single-read / single-write. Each thread owns one spatial position
// and CPT=64 channels held in registers. Cross-group (4x) channel reduction
// through 2KB of shared memory. DRAM traffic = exactly 512 MiB.

constexpr int B_DIM  = 16;
constexpr int C_DIM  = 256;
constexpr int S_DIM  = 128 * 128;     // spatial size per (b,c)
constexpr int GROUPS = 4;             // channel groups per block
constexpr int CPT    = C_DIM / GROUPS; // 64 channels per thread
constexpr int LANES  = 128;           // spatial positions per block
constexpr int THREADS = GROUPS * LANES; // 512

__global__ __launch_bounds__(THREADS, 1)
void neighbour_channels_kernel(const float* __restrict__ x,
                               float* __restrict__ out)
{
    __shared__ float red[GROUPS][LANES];

    const int lane = threadIdx.x & (LANES - 1);   // spatial lane within tile
    const int grp  = threadIdx.x / LANES;         // channel group 0..3

    const int tiles_per_b = S_DIM / LANES;        // 128
    const int tile = blockIdx.x % tiles_per_b;
    const int b    = blockIdx.x / tiles_per_b;

    const long long spatial = (long long)tile * LANES + lane;
    const long long base    = (long long)b * C_DIM * S_DIM
                            + (long long)grp * CPT * S_DIM
                            + spatial;

    const float* __restrict__ xp = x + base;

    // Load CPT channels for this spatial position into registers.
    float v[CPT];
    float sum = 0.0f;
#pragma unroll
    for (int i = 0; i < CPT; ++i) {
        v[i] = xp[(long long)i * S_DIM];
    }
#pragma unroll
    for (int i = 0; i < CPT; ++i) {
        sum += v[i];
    }

    // Reduce partial sums across the 4 channel groups (same spatial lane).
    red[grp][lane] = sum;
    __syncthreads();
    const float total = red[0][lane] + red[1][lane] + red[2][lane] + red[3][lane];

    // Write out = total - x, all from registers (no second read of x).
    float* __restrict__ op = out + base;
#pragma unroll
    for (int i = 0; i < CPT; ++i) {
        op[(long long)i * S_DIM] = total - v[i];
    }
}

extern "C" void kernel_launch(void* const* d_in, const int* in_sizes, int n_in,
                              void* d_out, int out_size)
{
    const float* x = (const float*)d_in[0];
    float* out = (float*)d_out;

    const int grid = B_DIM * (S_DIM / LANES); // 16 * 128 = 2048 blocks
    neighbour_channels_kernel<<<grid, THREADS>>>(x, out);
}

// round 2
// speedup vs baseline: 1.1933x; 1.1933x over previous
#include <cuda_runtime.h>

// out[b,i,h,w] = sum_j x[b,j,h,w] - x[b,i,h,w]
// x: fp32 [16, 256, 128, 128]
//
// Single-read / single-write, register-resident channel values.
// Block = 16 channel-groups x 32 lanes; each lane owns a float2 (2 spatial
// positions) and 16 channels => 32 regs of payload. __launch_bounds__(512,2)
// keeps regs <= 64 so TWO blocks co-reside per SM, overlapping one block's
// store phase with the other's load phase (the R1 kernel had 1 block/SM and
// the whole chip alternated read-burst / write-burst, capping DRAM at 66%).

constexpr int B_DIM  = 16;
constexpr int C_DIM  = 256;
constexpr int S_DIM  = 128 * 128;        // spatial per (b,c)
constexpr int GROUPS = 16;               // channel groups per block
constexpr int CPT    = C_DIM / GROUPS;   // 16 channels per thread
constexpr int LANES  = 32;               // float2 lanes per group
constexpr int VEC    = 2;                // floats per lane (float2)
constexpr int SPB    = LANES * VEC;      // 64 spatial positions per block
constexpr int THREADS = GROUPS * LANES;  // 512

__global__ __launch_bounds__(THREADS, 2)
void neighbour_channels_kernel(const float* __restrict__ x,
                               float* __restrict__ out)
{
    __shared__ float2 red[GROUPS][LANES];

    const int lane = threadIdx.x & (LANES - 1);
    const int grp  = threadIdx.x >> 5;           // 0..15

    const int tiles_per_b = S_DIM / SPB;         // 256
    const int tile = blockIdx.x % tiles_per_b;
    const int b    = blockIdx.x / tiles_per_b;

    const long long spatial = (long long)tile * SPB + lane * VEC;
    const long long base    = (long long)b * C_DIM * S_DIM
                            + (long long)grp * CPT * S_DIM
                            + spatial;

    const float2* __restrict__ xp = (const float2*)(x + base);

    // Load CPT channels (float2 each) into registers, channel stride S_DIM/2
    // in float2 units.
    float2 v[CPT];
#pragma unroll
    for (int i = 0; i < CPT; ++i) {
        v[i] = xp[(long long)i * (S_DIM / 2)];
    }

    float2 sum = make_float2(0.0f, 0.0f);
#pragma unroll
    for (int i = 0; i < CPT; ++i) {
        sum.x += v[i].x;
        sum.y += v[i].y;
    }

    // Cross-group reduction: 16 partials per lane.
    red[grp][lane] = sum;
    __syncthreads();

    float2 total = make_float2(0.0f, 0.0f);
#pragma unroll
    for (int g = 0; g < GROUPS; ++g) {
        float2 p = red[g][lane];
        total.x += p.x;
        total.y += p.y;
    }

    // Write out = total - x from registers (no second global read).
    float2* __restrict__ op = (float2*)(out + base);
#pragma unroll
    for (int i = 0; i < CPT; ++i) {
        float2 o;
        o.x = total.x - v[i].x;
        o.y = total.y - v[i].y;
        op[(long long)i * (S_DIM / 2)] = o;
    }
}

extern "C" void kernel_launch(void* const* d_in, const int* in_sizes, int n_in,
                              void* d_out, int out_size)
{
    const float* x = (const float*)d_in[0];
    float* out = (float*)d_out;

    const int grid = B_DIM * (S_DIM / SPB);  // 16 * 256 = 4096 blocks
    neighbour_channels_kernel<<<grid, THREADS>>>(x, out);
}